// round 6
// baseline (speedup 1.0000x reference)
#include <cuda_runtime.h>

// Problem constants
#define BB 4
#define SQ 4096
#define SK 462
#define HH 10
#define DH 64
#define DD 640   // HH*DH

// Tiling
#define QT 32        // queries per block
#define CK 128       // key chunk
#define NCHUNK 4     // ceil(462/128): 128,128,128,78

// SMEM row strides (floats) — chosen for bank-conflict-free access
#define SP 468       // S rows
#define QP 65        // Q rows
#define KP 65        // K rows
#define VP 64        // V rows (d-split {4g, 32+4g} covers all 32 banks per LDS.128)

#define NTHREADS 256

#define S_OFF   0
#define Q_OFF   (QT*SP)                 // 14976
#define KV_OFF  (Q_OFF + QT*QP)         // +2080
#define L_OFF   (KV_OFF + CK*KP)        // +8320
#define SMEM_FLOATS (L_OFF + QT)        // 25408 floats = 101632 B

__global__ __launch_bounds__(NTHREADS, 2)
void omost_attn_kernel(const float* __restrict__ qg_,
                       const float* __restrict__ kg_,
                       const float* __restrict__ vg_,
                       const int* __restrict__ mbm,      // mask_bool as int32 (harness dtype)
                       const float* __restrict__ msc,
                       float* __restrict__ outp)
{
    extern __shared__ float sm[];
    float* S    = sm + S_OFF;    // [QT][SP]  scores -> probabilities
    float* Qs   = sm + Q_OFF;    // [QT][QP]
    float* KV   = sm + KV_OFF;   // K: [CK][KP] / V: [CK][VP] (reused)
    float* Linv = sm + L_OFF;    // [QT]

    const int t  = threadIdx.x;
    const int q0 = blockIdx.x * QT;
    const int h  = blockIdx.y;
    const int b  = blockIdx.z;

    const float NEG_INF = __int_as_float(0xff800000);

    // ---- load Q tile [QT x DH] ----
    const float* qg = qg_ + ((size_t)(b * SQ + q0)) * DD + h * DH;
    for (int idx = t; idx < QT * DH; idx += NTHREADS) {
        int qq = idx >> 6, dd = idx & 63;
        Qs[qq * QP + dd] = qg[(size_t)qq * DD + dd];
    }
    __syncthreads();

    // ---- phase 1: S = Q K^T ----
    const float* kg = kg_ + ((size_t)b * SK) * DD + h * DH;
    const int qgrp = t & 7;    // 8 groups of 4 q  -> 32 q
    const int kgrp = t >> 3;   // 32 groups of 4 k -> 128 k

    for (int c = 0; c < NCHUNK; c++) {
        const int kbase = c * CK;
        const int ck = min(CK, SK - kbase);

        // fill K chunk (zero-pad tail rows)
        for (int idx = t; idx < CK * DH; idx += NTHREADS) {
            int kk = idx >> 6, dd = idx & 63;
            KV[kk * KP + dd] = (kk < ck) ? kg[(size_t)(kbase + kk) * DD + dd] : 0.0f;
        }
        __syncthreads();

        float acc[4][4];
        #pragma unroll
        for (int i = 0; i < 4; i++)
            #pragma unroll
            for (int j = 0; j < 4; j++) acc[i][j] = 0.0f;

        const float* qrow = Qs + (4 * qgrp) * QP;
        const float* krow = KV + (4 * kgrp) * KP;

        #pragma unroll 8
        for (int dd = 0; dd < DH; dd++) {
            float qv0 = qrow[0 * QP + dd];
            float qv1 = qrow[1 * QP + dd];
            float qv2 = qrow[2 * QP + dd];
            float qv3 = qrow[3 * QP + dd];
            float kv0 = krow[0 * KP + dd];
            float kv1 = krow[1 * KP + dd];
            float kv2 = krow[2 * KP + dd];
            float kv3 = krow[3 * KP + dd];
            acc[0][0] += qv0 * kv0; acc[0][1] += qv0 * kv1;
            acc[0][2] += qv0 * kv2; acc[0][3] += qv0 * kv3;
            acc[1][0] += qv1 * kv0; acc[1][1] += qv1 * kv1;
            acc[1][2] += qv1 * kv2; acc[1][3] += qv1 * kv3;
            acc[2][0] += qv2 * kv0; acc[2][1] += qv2 * kv1;
            acc[2][2] += qv2 * kv2; acc[2][3] += qv2 * kv3;
            acc[3][0] += qv3 * kv0; acc[3][1] += qv3 * kv1;
            acc[3][2] += qv3 * kv2; acc[3][3] += qv3 * kv3;
        }

        #pragma unroll
        for (int i = 0; i < 4; i++) {
            #pragma unroll
            for (int j = 0; j < 4; j++) {
                int col = kbase + 4 * kgrp + j;
                if (col < SK) S[(4 * qgrp + i) * SP + col] = acc[i][j];
            }
        }
        __syncthreads();
    }

    // ---- phase 2: mask + softmax (each warp owns 4 query rows) ----
    {
        const int warp = t >> 5, lane = t & 31;
        for (int qq = warp * 4; qq < warp * 4 + 4; qq++) {
            const size_t moff = (((size_t)(b * HH + h)) * SQ + (q0 + qq)) * (size_t)SK;
            float* Srow = S + qq * SP;

            float mmax = NEG_INF;
            for (int kk = lane; kk < SK; kk += 32) {
                float s = Srow[kk] * (0.125f * msc[moff + kk]);
                s = (mbm[moff + kk] != 0) ? s : NEG_INF;
                Srow[kk] = s;
                mmax = fmaxf(mmax, s);
            }
            #pragma unroll
            for (int o = 16; o > 0; o >>= 1)
                mmax = fmaxf(mmax, __shfl_xor_sync(0xffffffffu, mmax, o));

            float lsum = 0.0f;
            for (int kk = lane; kk < SK; kk += 32) {
                float p = __expf(Srow[kk] - mmax);
                Srow[kk] = p;
                lsum += p;
            }
            #pragma unroll
            for (int o = 16; o > 0; o >>= 1)
                lsum += __shfl_xor_sync(0xffffffffu, lsum, o);

            if (lane == 0) Linv[qq] = 1.0f / lsum;
        }
    }
    __syncthreads();

    // ---- phase 3: O = P V ----
    const int pq   = t >> 3;  // 0..31  query row
    const int dgrp = t & 7;   // 0..7   owns d in {4g..4g+3} U {32+4g..32+4g+3}
    float a0 = 0.f, a1 = 0.f, a2 = 0.f, a3 = 0.f;
    float a4 = 0.f, a5 = 0.f, a6 = 0.f, a7 = 0.f;

    const float* vg = vg_ + ((size_t)b * SK) * DD + h * DH;
    float4* KV4 = reinterpret_cast<float4*>(KV);

    for (int c = 0; c < NCHUNK; c++) {
        const int kbase = c * CK;
        const int ck = min(CK, SK - kbase);

        // fill V chunk (stride VP=64, vectorized)
        for (int idx = t; idx < CK * (DH / 4); idx += NTHREADS) {
            int kk = idx >> 4, d4 = idx & 15;
            if (kk < ck)
                KV4[kk * (VP / 4) + d4] =
                    *reinterpret_cast<const float4*>(vg + (size_t)(kbase + kk) * DD + d4 * 4);
        }
        __syncthreads();

        const float* Prow = S + pq * SP + kbase;
        #pragma unroll 2
        for (int kk = 0; kk < ck; kk++) {
            float p = Prow[kk];
            const float* vr = KV + kk * VP;
            float4 v0 = *reinterpret_cast<const float4*>(vr + 4 * dgrp);
            float4 v1 = *reinterpret_cast<const float4*>(vr + 32 + 4 * dgrp);
            a0 += p * v0.x; a1 += p * v0.y; a2 += p * v0.z; a3 += p * v0.w;
            a4 += p * v1.x; a5 += p * v1.y; a6 += p * v1.z; a7 += p * v1.w;
        }
        __syncthreads();
    }

    // ---- writeout (normalize by row sum) ----
    const float li = Linv[pq];
    float* og = outp + ((size_t)(b * SQ + q0 + pq)) * DD + h * DH;
    float4 o0 = make_float4(a0 * li, a1 * li, a2 * li, a3 * li);
    float4 o1 = make_float4(a4 * li, a5 * li, a6 * li, a7 * li);
    *reinterpret_cast<float4*>(og + 4 * dgrp) = o0;
    *reinterpret_cast<float4*>(og + 32 + 4 * dgrp) = o1;
}

extern "C" void kernel_launch(void* const* d_in, const int* in_sizes, int n_in,
                              void* d_out, int out_size)
{
    (void)in_sizes; (void)n_in; (void)out_size;
    const float* q = (const float*)d_in[0];
    const float* k = (const float*)d_in[1];
    const float* v = (const float*)d_in[2];
    const int*   mb = (const int*)d_in[3];     // mask_bool arrives as int32
    const float* ms = (const float*)d_in[4];
    float* out = (float*)d_out;

    cudaFuncSetAttribute(omost_attn_kernel,
                         cudaFuncAttributeMaxDynamicSharedMemorySize,
                         SMEM_FLOATS * (int)sizeof(float));

    dim3 grid(SQ / QT, HH, BB);
    omost_attn_kernel<<<grid, NTHREADS, SMEM_FLOATS * sizeof(float)>>>(q, k, v, mb, ms, out);
}

// round 7
// speedup vs baseline: 1.4636x; 1.4636x over previous
#include <cuda_runtime.h>

// Problem constants
#define BB 4
#define SQ 4096
#define SK 462
#define HH 10
#define DH 64
#define DD 640   // HH*DH

// Tiling
#define QT 32        // queries per block
#define CK 128       // key chunk
#define NCHUNK 4     // ceil(462/128)

// SMEM strides (floats). QP/KP = 68: mult of 4 (16B rows) and 68 mod 32 = 4
// -> with q rows qgrp+8i / k rows kgrp+32j, LDS.128 bank-group starts are
// 4*qgrp mod 32: all 8 distinct -> conflict-free.
#define SP 468
#define QP 68
#define KP 68
#define VP 64

#define NTHREADS 256

#define S_OFF   0
#define Q_OFF   (QT*SP)                  // 14976
#define KV_OFF  (Q_OFF + QT*QP)          // +2176 = 17152
#define L_OFF   (KV_OFF + CK*KP)         // +8704 = 25856
#define SMEM_FLOATS (L_OFF + QT)         // 25888 floats = 103552 B

// packed f32x2 FMA: acc.{lo,hi} += a.{lo,hi} * b.{lo,hi}
__device__ __forceinline__ void ffma2(unsigned long long& acc,
                                      unsigned long long a,
                                      unsigned long long b)
{
    asm("fma.rn.f32x2 %0, %1, %2, %0;" : "+l"(acc) : "l"(a), "l"(b));
}

__device__ __forceinline__ unsigned long long dup2(float x)
{
    unsigned long long r;
    asm("mov.b64 %0, {%1, %1};" : "=l"(r) : "r"(__float_as_uint(x)));
    return r;
}

__device__ __forceinline__ float hsum2(unsigned long long a)
{
    float lo = __int_as_float((unsigned int)(a & 0xffffffffull));
    float hi = __int_as_float((unsigned int)(a >> 32));
    return lo + hi;
}

__global__ __launch_bounds__(NTHREADS, 2)
void omost_attn_kernel(const float* __restrict__ qg_,
                       const float* __restrict__ kg_,
                       const float* __restrict__ vg_,
                       const int* __restrict__ mbm,
                       const float* __restrict__ msc,
                       float* __restrict__ outp)
{
    extern __shared__ float sm[];
    float* S    = sm + S_OFF;    // [QT][SP]
    float* Qs   = sm + Q_OFF;    // [QT][QP]
    float* KV   = sm + KV_OFF;   // K: [CK][KP] / V: [CK][VP]
    float* Linv = sm + L_OFF;    // [QT]

    const int t  = threadIdx.x;
    const int q0 = blockIdx.x * QT;
    const int h  = blockIdx.y;
    const int b  = blockIdx.z;

    const float NEG_INF = __int_as_float(0xff800000);

    // ---- load Q tile [QT x DH] (vectorized) ----
    const float* qg = qg_ + ((size_t)(b * SQ + q0)) * DD + h * DH;
    {
        float4* Qs4 = reinterpret_cast<float4*>(Qs);
        for (int idx = t; idx < QT * (DH / 4); idx += NTHREADS) {
            int qq = idx >> 4, d4 = idx & 15;
            Qs4[qq * (QP / 4) + d4] =
                *reinterpret_cast<const float4*>(qg + (size_t)qq * DD + d4 * 4);
        }
    }
    __syncthreads();

    // ---- phase 1: S = Q K^T  (f32x2 packed along dd) ----
    const float* kg = kg_ + ((size_t)b * SK) * DD + h * DH;
    const int qgrp = t & 7;    // q rows: qgrp + 8*i
    const int kgrp = t >> 3;   // k rows: kgrp + 32*j

    for (int c = 0; c < NCHUNK; c++) {
        const int kbase = c * CK;
        const int ck = min(CK, SK - kbase);

        // fill K chunk (zero-pad tail rows), vectorized
        {
            float4* KV4 = reinterpret_cast<float4*>(KV);
            const float4 z4 = make_float4(0.f, 0.f, 0.f, 0.f);
            for (int idx = t; idx < CK * (DH / 4); idx += NTHREADS) {
                int kk = idx >> 4, d4 = idx & 15;
                KV4[kk * (KP / 4) + d4] = (kk < ck)
                    ? *reinterpret_cast<const float4*>(kg + (size_t)(kbase + kk) * DD + d4 * 4)
                    : z4;
            }
        }
        __syncthreads();

        unsigned long long acc[4][4];
        #pragma unroll
        for (int i = 0; i < 4; i++)
            #pragma unroll
            for (int j = 0; j < 4; j++) acc[i][j] = 0ull;

        const float* qbase = Qs + qgrp * QP;
        const float* kbse  = KV + kgrp * KP;

        #pragma unroll 4
        for (int dq = 0; dq < DH / 4; dq++) {
            ulonglong2 qv[4], kv[4];
            #pragma unroll
            for (int i = 0; i < 4; i++)
                qv[i] = *reinterpret_cast<const ulonglong2*>(qbase + (8 * i) * QP + 4 * dq);
            #pragma unroll
            for (int j = 0; j < 4; j++)
                kv[j] = *reinterpret_cast<const ulonglong2*>(kbse + (32 * j) * KP + 4 * dq);

            #pragma unroll
            for (int i = 0; i < 4; i++)
                #pragma unroll
                for (int j = 0; j < 4; j++) {
                    ffma2(acc[i][j], qv[i].x, kv[j].x);
                    ffma2(acc[i][j], qv[i].y, kv[j].y);
                }
        }

        #pragma unroll
        for (int i = 0; i < 4; i++) {
            #pragma unroll
            for (int j = 0; j < 4; j++) {
                int col = kbase + kgrp + 32 * j;
                if (col < SK) S[(qgrp + 8 * i) * SP + col] = hsum2(acc[i][j]);
            }
        }
        __syncthreads();
    }

    // ---- phase 2: mask + softmax (each warp owns 4 query rows) ----
    {
        const int warp = t >> 5, lane = t & 31;
        for (int qq = warp * 4; qq < warp * 4 + 4; qq++) {
            const size_t moff = (((size_t)(b * HH + h)) * SQ + (q0 + qq)) * (size_t)SK;
            float* Srow = S + qq * SP;

            float mmax = NEG_INF;
            for (int kk = lane; kk < SK; kk += 32) {
                float s = Srow[kk] * (0.125f * msc[moff + kk]);
                s = (mbm[moff + kk] != 0) ? s : NEG_INF;
                Srow[kk] = s;
                mmax = fmaxf(mmax, s);
            }
            #pragma unroll
            for (int o = 16; o > 0; o >>= 1)
                mmax = fmaxf(mmax, __shfl_xor_sync(0xffffffffu, mmax, o));

            float lsum = 0.0f;
            for (int kk = lane; kk < SK; kk += 32) {
                float p = __expf(Srow[kk] - mmax);
                Srow[kk] = p;
                lsum += p;
            }
            #pragma unroll
            for (int o = 16; o > 0; o >>= 1)
                lsum += __shfl_xor_sync(0xffffffffu, lsum, o);

            if (lane == 0) Linv[qq] = 1.0f / lsum;
        }
    }
    __syncthreads();

    // ---- phase 3: O = P V  (2 q-rows x 4 d per thread, f32x2 along d) ----
    const int pq2  = t >> 4;  // 0..15 -> q rows 2*pq2, 2*pq2+1
    const int dgrp = t & 15;  // 0..15 -> d = 4*dgrp .. 4*dgrp+3

    unsigned long long a00 = 0ull, a01 = 0ull;  // q row 0: d pairs
    unsigned long long a10 = 0ull, a11 = 0ull;  // q row 1

    const float* vg = vg_ + ((size_t)b * SK) * DD + h * DH;

    for (int c = 0; c < NCHUNK; c++) {
        const int kbase = c * CK;
        const int ck = min(CK, SK - kbase);

        // fill V chunk (vectorized)
        {
            float4* KV4 = reinterpret_cast<float4*>(KV);
            for (int idx = t; idx < CK * (DH / 4); idx += NTHREADS) {
                int kk = idx >> 4, d4 = idx & 15;
                if (kk < ck)
                    KV4[kk * (VP / 4) + d4] =
                        *reinterpret_cast<const float4*>(vg + (size_t)(kbase + kk) * DD + d4 * 4);
            }
        }
        __syncthreads();

        const float* P0 = S + (2 * pq2) * SP + kbase;
        const float* P1 = S + (2 * pq2 + 1) * SP + kbase;
        const float* Vb = KV + 4 * dgrp;

        #pragma unroll 4
        for (int kk = 0; kk < ck; kk++) {
            unsigned long long p0 = dup2(P0[kk]);
            unsigned long long p1 = dup2(P1[kk]);
            ulonglong2 v = *reinterpret_cast<const ulonglong2*>(Vb + kk * VP);
            ffma2(a00, p0, v.x);
            ffma2(a01, p0, v.y);
            ffma2(a10, p1, v.x);
            ffma2(a11, p1, v.y);
        }
        __syncthreads();
    }

    // ---- writeout ----
    {
        const float li0 = Linv[2 * pq2];
        const float li1 = Linv[2 * pq2 + 1];
        float* og0 = outp + ((size_t)(b * SQ + q0 + 2 * pq2)) * DD + h * DH + 4 * dgrp;
        float* og1 = og0 + DD;

        float2 lo0, hi0, lo1, hi1;
        lo0.x = __int_as_float((unsigned)(a00 & 0xffffffffull));
        lo0.y = __int_as_float((unsigned)(a00 >> 32));
        hi0.x = __int_as_float((unsigned)(a01 & 0xffffffffull));
        hi0.y = __int_as_float((unsigned)(a01 >> 32));
        lo1.x = __int_as_float((unsigned)(a10 & 0xffffffffull));
        lo1.y = __int_as_float((unsigned)(a10 >> 32));
        hi1.x = __int_as_float((unsigned)(a11 & 0xffffffffull));
        hi1.y = __int_as_float((unsigned)(a11 >> 32));

        *reinterpret_cast<float4*>(og0) =
            make_float4(lo0.x * li0, lo0.y * li0, hi0.x * li0, hi0.y * li0);
        *reinterpret_cast<float4*>(og1) =
            make_float4(lo1.x * li1, lo1.y * li1, hi1.x * li1, hi1.y * li1);
    }
}

extern "C" void kernel_launch(void* const* d_in, const int* in_sizes, int n_in,
                              void* d_out, int out_size)
{
    (void)in_sizes; (void)n_in; (void)out_size;
    const float* q = (const float*)d_in[0];
    const float* k = (const float*)d_in[1];
    const float* v = (const float*)d_in[2];
    const int*   mb = (const int*)d_in[3];
    const float* ms = (const float*)d_in[4];
    float* out = (float*)d_out;

    cudaFuncSetAttribute(omost_attn_kernel,
                         cudaFuncAttributeMaxDynamicSharedMemorySize,
                         SMEM_FLOATS * (int)sizeof(float));

    dim3 grid(SQ / QT, HH, BB);
    omost_attn_kernel<<<grid, NTHREADS, SMEM_FLOATS * sizeof(float)>>>(q, k, v, mb, ms, out);
}